// round 8
// baseline (speedup 1.0000x reference)
#include <cuda_runtime.h>
#include <math.h>

#define NSI 120
#define NS2 (NSI*NSI)      // 14400
#define NS3 (NSI*NSI*NSI)  // 1728000
#define RKY 61             // ky 0..60 (Hermitian half, y axis)
#define NROWS (NSI*RKY)    // 7320 (kx,ky) rows
#define ALPHA_F 1.0f
#define PI_D 3.14159265358979323846

typedef unsigned long long u64;

// ---------------- scratch (static device globals; no allocation) ----------------
__device__ __align__(16) float  g_mesh[NS3 + 8];
__device__ __align__(16) float2 g_buf1[NSI*RKY*NSI];   // [(x*61+ky)*120+z]
__device__ __align__(16) float2 g_buf2[NSI*NROWS];     // z-major: [z*7320 + kx*61+ky]
__device__ float  g_invc[9];
__device__ double g_vol;
__device__ double g_acc[3];    // [0]=Sum |S|^2 G, [1]=sum q, [2]=sum q^2
__device__ float2 g_tw[NSI];   // exp(-2*pi*i*t/120)

// ---------------- packed f32x2 helpers ----------------
__device__ __forceinline__ u64 pk2(float x, float y) {
    u64 r; asm("mov.b64 %0, {%1, %2};" : "=l"(r) : "f"(x), "f"(y)); return r;
}
__device__ __forceinline__ void upk2(u64 v, float& x, float& y) {
    asm("mov.b64 {%0, %1}, %2;" : "=f"(x), "=f"(y) : "l"(v));
}
__device__ __forceinline__ void fma2(u64& d, u64 a, u64 b) {
    asm("fma.rn.f32x2 %0, %1, %2, %3;" : "=l"(d) : "l"(a), "l"(b), "l"(d));
}

// ---------------- vector global reductions (sm_90+) ----------------
__device__ __forceinline__ void red2(float* p, float a, float b) {
    asm volatile("red.global.add.v2.f32 [%0], {%1, %2};"
                 :: "l"(p), "f"(a), "f"(b) : "memory");
}
__device__ __forceinline__ void red4(float* p, float a, float b, float c, float d) {
    asm volatile("red.global.add.v4.f32 [%0], {%1, %2, %3, %4};"
                 :: "l"(p), "f"(a), "f"(b), "f"(c), "f"(d) : "memory");
}

// ---------------- setup ----------------
__global__ void setup_kernel(const float* __restrict__ box) {
    int t = threadIdx.x;
    if (t < NSI) {
        double ang = -2.0 * PI_D * (double)t / (double)NSI;
        g_tw[t] = make_float2((float)cos(ang), (float)sin(ang));
    }
    if (t == 0) {
        double b[9];
        for (int i = 0; i < 9; i++) b[i] = (double)box[i];
        double c00 =  (b[4]*b[8] - b[5]*b[7]);
        double c01 = -(b[3]*b[8] - b[5]*b[6]);
        double c02 =  (b[3]*b[7] - b[4]*b[6]);
        double c10 = -(b[1]*b[8] - b[2]*b[7]);
        double c11 =  (b[0]*b[8] - b[2]*b[6]);
        double c12 = -(b[0]*b[7] - b[1]*b[6]);
        double c20 =  (b[1]*b[5] - b[2]*b[4]);
        double c21 = -(b[0]*b[5] - b[2]*b[3]);
        double c22 =  (b[0]*b[4] - b[1]*b[3]);
        double det = b[0]*c00 + b[1]*c01 + b[2]*c02;
        g_invc[0] = (float)(c00/det); g_invc[1] = (float)(c10/det); g_invc[2] = (float)(c20/det);
        g_invc[3] = (float)(c01/det); g_invc[4] = (float)(c11/det); g_invc[5] = (float)(c21/det);
        g_invc[6] = (float)(c02/det); g_invc[7] = (float)(c12/det); g_invc[8] = (float)(c22/det);
        g_vol = fabs(det);
        g_acc[0] = 0.0; g_acc[1] = 0.0; g_acc[2] = 0.0;
    }
}

__global__ void zero_mesh_kernel() {
    int i = blockIdx.x * blockDim.x + threadIdx.x;
    float4* p = (float4*)g_mesh;
    if (i < (NS3 + 8)/4) p[i] = make_float4(0.f, 0.f, 0.f, 0.f);
}

// ---------------- order-6 Lagrange weights, nodes t_j = j - 2.5 ----------------
__device__ __forceinline__ void lag6(float x, float* w) {
    float d0 = x + 2.5f, d1 = x + 1.5f, d2 = x + 0.5f;
    float d3 = x - 0.5f, d4 = x - 1.5f, d5 = x - 2.5f;
    float p1 = d0, p2 = p1*d1, p3 = p2*d2, p4 = p3*d3, p5 = p4*d4;
    float s4 = d5, s3 = s4*d4, s2 = s3*d3, s1 = s2*d2, s0 = s1*d1;
    w[0] = s0      * (-1.f/120.f);
    w[1] = p1 * s1 * ( 1.f/24.f);
    w[2] = p2 * s2 * (-1.f/12.f);
    w[3] = p3 * s3 * ( 1.f/12.f);
    w[4] = p4 * s4 * (-1.f/24.f);
    w[5] = p5      * ( 1.f/120.f);
}

__device__ __forceinline__ int wrap120(int v) {
    return (v < 0) ? v + NSI : ((v >= NSI) ? v - NSI : v);
}

// ---------------- spread: one thread per atom, vector reductions --------------
__global__ void spread_kernel(const float* __restrict__ coords,
                              const float* __restrict__ charges, int n) {
    int i = blockIdx.x * blockDim.x + threadIdx.x;
    float q = 0.f;
    float wx[6], wy[6], wz[6];
    int gx[6], gy[6], gz[6];
    int z0w = 0;
    bool act = (i < n);
    if (act) {
        float c0 = coords[3*i], c1 = coords[3*i+1], c2 = coords[3*i+2];
        q = charges[i];
        float fx = c0*g_invc[0] + c1*g_invc[3] + c2*g_invc[6];
        float fy = c0*g_invc[1] + c1*g_invc[4] + c2*g_invc[7];
        float fz = c0*g_invc[2] + c1*g_invc[5] + c2*g_invc[8];
        float px = fx * (float)NSI, py = fy * (float)NSI, pz = fz * (float)NSI;
        float i0x = floorf(px), i0y = floorf(py), i0z = floorf(pz);
        lag6(px - i0x - 0.5f, wx);
        lag6(py - i0y - 0.5f, wy);
        lag6(pz - i0z - 0.5f, wz);
        int ix = (int)i0x, iy = (int)i0y, iz = (int)i0z;
        #pragma unroll
        for (int a = 0; a < 6; a++) {
            gx[a] = wrap120(ix + a - 2);
            gy[a] = wrap120(iy + a - 2);
            gz[a] = wrap120(iz + a - 2);
        }
        z0w = gz[0];
    }
    double dq = (double)q, dq2 = (double)q * (double)q;
    #pragma unroll
    for (int o = 16; o; o >>= 1) {
        dq  += __shfl_down_sync(0xffffffffu, dq,  o);
        dq2 += __shfl_down_sync(0xffffffffu, dq2, o);
    }
    if ((threadIdx.x & 31) == 0) {
        atomicAdd(&g_acc[1], dq);
        atomicAdd(&g_acc[2], dq2);
    }
    if (!act) return;

    bool zcontig = (z0w <= NSI - 6);
    int zmod = z0w & 3;

    #pragma unroll
    for (int a = 0; a < 6; a++) {
        int rowx = gx[a] * NS2;
        float wq = wx[a] * q;
        #pragma unroll
        for (int b = 0; b < 6; b++) {
            int row = rowx + gy[b] * NSI;
            float wxy = wq * wy[b];
            float v0 = wxy*wz[0], v1 = wxy*wz[1], v2 = wxy*wz[2];
            float v3 = wxy*wz[3], v4 = wxy*wz[4], v5 = wxy*wz[5];
            if (zcontig) {
                float* p = g_mesh + row + z0w;
                if (zmod == 0) {
                    red4(p, v0, v1, v2, v3);
                    red2(p + 4, v4, v5);
                } else if (zmod == 2) {
                    red2(p, v0, v1);
                    red4(p + 2, v2, v3, v4, v5);
                } else if (zmod == 3) {
                    atomicAdd(p, v0);
                    red4(p + 1, v1, v2, v3, v4);
                    atomicAdd(p + 5, v5);
                } else { // zmod == 1
                    red4(p - 1, 0.f, v0, v1, v2);
                    red4(p + 3, v3, v4, v5, 0.f);
                }
            } else {
                atomicAdd(&g_mesh[row + gz[0]], v0);
                atomicAdd(&g_mesh[row + gz[1]], v1);
                atomicAdd(&g_mesh[row + gz[2]], v2);
                atomicAdd(&g_mesh[row + gz[3]], v3);
                atomicAdd(&g_mesh[row + gz[4]], v4);
                atomicAdd(&g_mesh[row + gz[5]], v5);
            }
        }
    }
}

// ================= pass A: DFT along y (real->complex), smem-staged ===========
// one block per x. dyn smem: plane[14400] f32 + twp[60*64] u64 = 88320 B.
// thread (g=tid>>7, z=tid&127): g=0 -> ky chunks 0..3, g=1 -> 4..7.
#define SMEM_A (14400*4 + 60*64*8)
__global__ void __launch_bounds__(256) passA_kernel() {
    extern __shared__ __align__(16) char smraw[];
    float* plane = (float*)smraw;                 // 14400 floats
    u64*   twp   = (u64*)(smraw + 14400*4);       // [y*64 + ky]
    int x = blockIdx.x;
    int tid = threadIdx.x;

    const float4* src = (const float4*)(g_mesh + x * NS2);
    float4* dst = (float4*)plane;
    for (int i = tid; i < 3600; i += 256) dst[i] = src[i];
    for (int i = tid; i < 60 * RKY; i += 256) {
        int y = i / RKY, ky = i % RKY;
        float2 t = g_tw[(ky * y) % NSI];
        twp[y * 64 + ky] = pk2(t.x, t.y);
    }
    __syncthreads();

    int g = tid >> 7;
    int z = tid & 127;
    if (z >= NSI) return;
    float v0  = plane[z];
    float v60 = plane[60 * NSI + z];
    for (int kc = g * 4; kc < g * 4 + 4; kc++) {
        int kybase = kc * 8;
        u64 acc[8];
        #pragma unroll
        for (int c = 0; c < 8; c++) acc[c] = pk2(0.f, 0.f);
        for (int yp = 1; yp < 60; yp++) {
            float a = plane[yp * NSI + z];
            float b = plane[(NSI - yp) * NSI + z];
            u64 uw = pk2(a + b, a - b);
            const ulonglong2* t = (const ulonglong2*)&twp[yp * 64 + kybase];
            #pragma unroll
            for (int j = 0; j < 4; j++) {
                ulonglong2 tv = t[j];
                fma2(acc[2*j  ], uw, tv.x);
                fma2(acc[2*j+1], uw, tv.y);
            }
        }
        #pragma unroll
        for (int c = 0; c < 8; c++) {
            int ky = kybase + c;
            if (ky < RKY) {
                float ax, ay; upk2(acc[c], ax, ay);
                float sgn = (ky & 1) ? -1.f : 1.f;
                float sx = ax + v0 + sgn * v60;
                g_buf1[(x * RKY + ky) * NSI + z] = make_float2(sx, ay);
            }
        }
    }
}

// ================= pass B: DFT along x (complex), smem-staged =================
// one block per (zh, ky). dyn smem: plane[120x*60z] f2 + twp[60*256] u64 = 180480 B.
// thread (kg=tid>>6, zl=tid&63): kg handles kx chunks kg*4..min(+4,15).
#define SMEM_B (120*60*8 + 60*256*8)
__global__ void __launch_bounds__(256) passB_kernel() {
    extern __shared__ __align__(16) char smraw[];
    float2* plane = (float2*)smraw;                 // [x*60 + zl]
    u64*    twp   = (u64*)(smraw + 120*60*8);       // [xp*256 + kx*2 (+1)]
    int zh = blockIdx.x;           // 0/1
    int ky = blockIdx.y;
    int tid = threadIdx.x;

    for (int i = tid; i < 120 * 60; i += 256) {
        int xx = i / 60, zl = i % 60;
        plane[i] = g_buf1[(xx * RKY + ky) * NSI + zh * 60 + zl];
    }
    for (int i = tid; i < 60 * NSI; i += 256) {
        int xp = i / NSI, kx = i % NSI;
        float2 t = g_tw[(kx * xp) % NSI];
        twp[xp * 256 + kx * 2    ] = pk2(t.x, t.x);
        twp[xp * 256 + kx * 2 + 1] = pk2(-t.y, t.y);
    }
    __syncthreads();

    int kg = tid >> 6;
    int zl = tid & 63;
    if (zl >= 60) return;
    int z = zh * 60 + zl;
    float2 v0  = plane[zl];              // x=0
    float2 v60 = plane[60 * 60 + zl];    // x=60
    int kc_end = kg * 4 + 4; if (kc_end > 15) kc_end = 15;
    for (int kc = kg * 4; kc < kc_end; kc++) {
        int kxbase = kc * 8;
        u64 acc[8];
        #pragma unroll
        for (int c = 0; c < 8; c++) acc[c] = pk2(0.f, 0.f);
        for (int xp = 1; xp < 60; xp++) {
            float2 a = plane[xp * 60 + zl];
            float2 b = plane[(NSI - xp) * 60 + zl];
            u64 u1 = pk2(a.x + b.x, a.y + b.y);   // (ux, uy)
            u64 u2 = pk2(a.y - b.y, a.x - b.x);   // (wy, wx)
            const ulonglong2* t = (const ulonglong2*)&twp[xp * 256 + kxbase * 2];
            #pragma unroll
            for (int c = 0; c < 8; c++) {
                ulonglong2 tv = t[c];
                fma2(acc[c], u1, tv.x);
                fma2(acc[c], u2, tv.y);
            }
        }
        #pragma unroll
        for (int c = 0; c < 8; c++) {
            int kx = kxbase + c;
            float ax, ay; upk2(acc[c], ax, ay);
            float sgn = (kx & 1) ? -1.f : 1.f;
            float sx = ax + v0.x + sgn * v60.x;
            float sy = ay + v0.y + sgn * v60.y;
            g_buf2[z * NROWS + kx * RKY + ky] = make_float2(sx, sy);
        }
    }
}

// ================= pass C: DFT along z fused with reduction, smem-staged ======
// one block per (kzh, rb). dyn smem: tile[120z*128r] f2 + twp[60*128] u64 = 184320 B.
// thread (kg=tid>>7, rl=tid&127): kg handles kz chunks kg*3..kg*3+3 of this half.
#define SMEM_C (120*128*8 + 60*128*8)
__global__ void __launch_bounds__(256) passC_kernel() {
    extern __shared__ __align__(16) char smraw[];
    float2* tile = (float2*)smraw;                  // [z*128 + rl]
    u64*    twp  = (u64*)(smraw + 120*128*8);       // [zp*128 + c*2 (+1)], c = kz local
    __shared__ double red[8];
    int kzh = blockIdx.x;          // 0/1
    int rb  = blockIdx.y;
    int rbase = rb * 128;
    int tid = threadIdx.x;

    for (int i = tid; i < 120 * 128; i += 256) {
        int z = i >> 7, rl = i & 127;
        int r = rbase + rl;
        tile[i] = (r < NROWS) ? g_buf2[z * NROWS + r] : make_float2(0.f, 0.f);
    }
    for (int i = tid; i < 60 * 60; i += 256) {
        int zp = i / 60, c = i % 60;
        int kz = kzh * 60 + c;
        float2 t = g_tw[(kz * zp) % NSI];
        twp[zp * 128 + c * 2    ] = pk2(t.x, t.x);
        twp[zp * 128 + c * 2 + 1] = pk2(-t.y, t.y);
    }
    __syncthreads();

    int kg = tid >> 7;
    int rl = tid & 127;
    int r = rbase + rl;
    bool act = (r < NROWS);
    float2 v0  = tile[rl];
    float2 v60 = tile[60 * 128 + rl];

    double contrib = 0.0;
    int kx = r / RKY, ky = r % RKY;
    int mx = (kx < 60) ? kx : kx - NSI;
    int my = (ky < 60) ? ky : ky - NSI;
    float wgt = (ky == 0 || ky == 60) ? 1.0f : 2.0f;
    float fmx = (float)mx, fmy = (float)my;
    const float twopi = 6.28318530717958647692f;

    for (int kc = kg * 3; kc < kg * 3 + 3; kc++) {
        int cbase = kc * 10;                 // local kz base within half
        u64 acc[10];
        #pragma unroll
        for (int c = 0; c < 10; c++) acc[c] = pk2(0.f, 0.f);
        for (int zp = 1; zp < 60; zp++) {
            float2 a = tile[zp * 128 + rl];
            float2 b = tile[(NSI - zp) * 128 + rl];
            u64 u1 = pk2(a.x + b.x, a.y + b.y);
            u64 u2 = pk2(a.y - b.y, a.x - b.x);
            const ulonglong2* t = (const ulonglong2*)&twp[zp * 128 + cbase * 2];
            #pragma unroll
            for (int c = 0; c < 10; c++) {
                ulonglong2 tv = t[c];
                fma2(acc[c], u1, tv.x);
                fma2(acc[c], u2, tv.y);
            }
        }
        if (act) {
            #pragma unroll
            for (int c = 0; c < 10; c++) {
                int kz = kzh * 60 + cbase + c;
                float sgn = (kz & 1) ? -1.f : 1.f;
                float ax, ay; upk2(acc[c], ax, ay);
                float sx = ax + v0.x + sgn * v60.x;
                float sy = ay + v0.y + sgn * v60.y;
                int mz = (kz < 60) ? kz : kz - NSI;
                float fmz = (float)mz;
                float k0 = twopi * (fmx * g_invc[0] + fmy * g_invc[1] + fmz * g_invc[2]);
                float k1 = twopi * (fmx * g_invc[3] + fmy * g_invc[4] + fmz * g_invc[5]);
                float k2 = twopi * (fmx * g_invc[6] + fmy * g_invc[7] + fmz * g_invc[8]);
                float ksq = k0*k0 + k1*k1 + k2*k2;
                float G = 0.f;
                if (ksq > 0.f)
                    G = 4.f * (float)PI_D * expf(-0.5f * ALPHA_F * ALPHA_F * ksq) / ksq;
                G *= wgt;
                contrib += (double)G * ((double)sx * (double)sx +
                                        (double)sy * (double)sy);
            }
        }
    }
    #pragma unroll
    for (int o = 16; o; o >>= 1)
        contrib += __shfl_down_sync(0xffffffffu, contrib, o);
    if ((tid & 31) == 0) red[tid >> 5] = contrib;
    __syncthreads();
    if (tid == 0) {
        double s = 0.0;
        #pragma unroll
        for (int w = 0; w < 8; w++) s += red[w];
        atomicAdd(&g_acc[0], s);
    }
}

// ---------------- finalize ----------------
__global__ void final_kernel(float* out) {
    double V  = g_vol;
    double A  = g_acc[0];
    double qs = g_acc[1];
    double q2 = g_acc[2];
    double E = 0.5 * ( A / V
                     - sqrt(2.0 / PI_D) / (double)ALPHA_F * q2
                     - 2.0 * PI_D * (double)(ALPHA_F * ALPHA_F) * qs * qs / V );
    out[0] = (float)E;
}

extern "C" void kernel_launch(void* const* d_in, const int* in_sizes, int n_in,
                              void* d_out, int out_size) {
    const float* coords  = (const float*)d_in[0];
    const float* box     = (const float*)d_in[1];
    const float* charges = (const float*)d_in[2];
    int n = in_sizes[2];   // N_ATOMS

    cudaFuncSetAttribute(passA_kernel, cudaFuncAttributeMaxDynamicSharedMemorySize, SMEM_A);
    cudaFuncSetAttribute(passB_kernel, cudaFuncAttributeMaxDynamicSharedMemorySize, SMEM_B);
    cudaFuncSetAttribute(passC_kernel, cudaFuncAttributeMaxDynamicSharedMemorySize, SMEM_C);

    setup_kernel<<<1, 128>>>(box);
    zero_mesh_kernel<<<((NS3 + 8)/4 + 255)/256, 256>>>();
    spread_kernel<<<(n + 127)/128, 128>>>(coords, charges, n);
    passA_kernel<<<NSI, 256, SMEM_A>>>();
    passB_kernel<<<dim3(2, RKY), 256, SMEM_B>>>();
    passC_kernel<<<dim3(2, (NROWS + 127)/128), 256, SMEM_C>>>();
    final_kernel<<<1, 1>>>((float*)d_out);
}

// round 9
// speedup vs baseline: 1.0504x; 1.0504x over previous
#include <cuda_runtime.h>
#include <math.h>

#define NSI 120
#define NS2 (NSI*NSI)      // 14400
#define NS3 (NSI*NSI*NSI)  // 1728000
#define RKY 61             // ky 0..60 (Hermitian half, y axis)
#define NROWS (NSI*RKY)    // 7320 (kx,ky) rows
#define ALPHA_F 1.0f
#define PI_D 3.14159265358979323846

typedef unsigned long long u64;

// ---------------- scratch (static device globals; no allocation) ----------------
__device__ __align__(16) float  g_mesh[NS3 + 8];
__device__ __align__(16) float2 g_buf1[NSI*RKY*NSI];   // [(x*61+ky)*120+z]
__device__ __align__(16) float2 g_buf2[NSI*NROWS];     // z-major: [z*7320 + kx*61+ky]
__device__ float  g_invc[9];
__device__ double g_vol;
__device__ double g_acc[3];    // [0]=Sum |S|^2 G, [1]=sum q, [2]=sum q^2
__device__ float2 g_tw[NSI];   // exp(-2*pi*i*t/120)

// ---------------- packed f32x2 helpers ----------------
__device__ __forceinline__ u64 pk2(float x, float y) {
    u64 r; asm("mov.b64 %0, {%1, %2};" : "=l"(r) : "f"(x), "f"(y)); return r;
}
__device__ __forceinline__ void upk2(u64 v, float& x, float& y) {
    asm("mov.b64 {%0, %1}, %2;" : "=f"(x), "=f"(y) : "l"(v));
}
__device__ __forceinline__ void fma2(u64& d, u64 a, u64 b) {
    asm("fma.rn.f32x2 %0, %1, %2, %3;" : "=l"(d) : "l"(a), "l"(b), "l"(d));
}

// ---------------- vector global reductions (sm_90+) ----------------
__device__ __forceinline__ void red2(float* p, float a, float b) {
    asm volatile("red.global.add.v2.f32 [%0], {%1, %2};"
                 :: "l"(p), "f"(a), "f"(b) : "memory");
}
__device__ __forceinline__ void red4(float* p, float a, float b, float c, float d) {
    asm volatile("red.global.add.v4.f32 [%0], {%1, %2, %3, %4};"
                 :: "l"(p), "f"(a), "f"(b), "f"(c), "f"(d) : "memory");
}

// ---------------- setup ----------------
__global__ void setup_kernel(const float* __restrict__ box) {
    int t = threadIdx.x;
    if (t < NSI) {
        double ang = -2.0 * PI_D * (double)t / (double)NSI;
        g_tw[t] = make_float2((float)cos(ang), (float)sin(ang));
    }
    if (t == 0) {
        double b[9];
        for (int i = 0; i < 9; i++) b[i] = (double)box[i];
        double c00 =  (b[4]*b[8] - b[5]*b[7]);
        double c01 = -(b[3]*b[8] - b[5]*b[6]);
        double c02 =  (b[3]*b[7] - b[4]*b[6]);
        double c10 = -(b[1]*b[8] - b[2]*b[7]);
        double c11 =  (b[0]*b[8] - b[2]*b[6]);
        double c12 = -(b[0]*b[7] - b[1]*b[6]);
        double c20 =  (b[1]*b[5] - b[2]*b[4]);
        double c21 = -(b[0]*b[5] - b[2]*b[3]);
        double c22 =  (b[0]*b[4] - b[1]*b[3]);
        double det = b[0]*c00 + b[1]*c01 + b[2]*c02;
        g_invc[0] = (float)(c00/det); g_invc[1] = (float)(c10/det); g_invc[2] = (float)(c20/det);
        g_invc[3] = (float)(c01/det); g_invc[4] = (float)(c11/det); g_invc[5] = (float)(c21/det);
        g_invc[6] = (float)(c02/det); g_invc[7] = (float)(c12/det); g_invc[8] = (float)(c22/det);
        g_vol = fabs(det);
        g_acc[0] = 0.0; g_acc[1] = 0.0; g_acc[2] = 0.0;
    }
}

__global__ void zero_mesh_kernel() {
    int i = blockIdx.x * blockDim.x + threadIdx.x;
    float4* p = (float4*)g_mesh;
    if (i < (NS3 + 8)/4) p[i] = make_float4(0.f, 0.f, 0.f, 0.f);
}

// ---------------- order-6 Lagrange weights, nodes t_j = j - 2.5 ----------------
__device__ __forceinline__ void lag6(float x, float* w) {
    float d0 = x + 2.5f, d1 = x + 1.5f, d2 = x + 0.5f;
    float d3 = x - 0.5f, d4 = x - 1.5f, d5 = x - 2.5f;
    float p1 = d0, p2 = p1*d1, p3 = p2*d2, p4 = p3*d3, p5 = p4*d4;
    float s4 = d5, s3 = s4*d4, s2 = s3*d3, s1 = s2*d2, s0 = s1*d1;
    w[0] = s0      * (-1.f/120.f);
    w[1] = p1 * s1 * ( 1.f/24.f);
    w[2] = p2 * s2 * (-1.f/12.f);
    w[3] = p3 * s3 * ( 1.f/12.f);
    w[4] = p4 * s4 * (-1.f/24.f);
    w[5] = p5      * ( 1.f/120.f);
}

__device__ __forceinline__ int wrap120(int v) {
    return (v < 0) ? v + NSI : ((v >= NSI) ? v - NSI : v);
}

// ---------------- spread: one thread per atom, vector reductions --------------
__global__ void spread_kernel(const float* __restrict__ coords,
                              const float* __restrict__ charges, int n) {
    int i = blockIdx.x * blockDim.x + threadIdx.x;
    float q = 0.f;
    float wx[6], wy[6], wz[6];
    int gx[6], gy[6], gz[6];
    int z0w = 0;
    bool act = (i < n);
    if (act) {
        float c0 = coords[3*i], c1 = coords[3*i+1], c2 = coords[3*i+2];
        q = charges[i];
        float fx = c0*g_invc[0] + c1*g_invc[3] + c2*g_invc[6];
        float fy = c0*g_invc[1] + c1*g_invc[4] + c2*g_invc[7];
        float fz = c0*g_invc[2] + c1*g_invc[5] + c2*g_invc[8];
        float px = fx * (float)NSI, py = fy * (float)NSI, pz = fz * (float)NSI;
        float i0x = floorf(px), i0y = floorf(py), i0z = floorf(pz);
        lag6(px - i0x - 0.5f, wx);
        lag6(py - i0y - 0.5f, wy);
        lag6(pz - i0z - 0.5f, wz);
        int ix = (int)i0x, iy = (int)i0y, iz = (int)i0z;
        #pragma unroll
        for (int a = 0; a < 6; a++) {
            gx[a] = wrap120(ix + a - 2);
            gy[a] = wrap120(iy + a - 2);
            gz[a] = wrap120(iz + a - 2);
        }
        z0w = gz[0];
    }
    double dq = (double)q, dq2 = (double)q * (double)q;
    #pragma unroll
    for (int o = 16; o; o >>= 1) {
        dq  += __shfl_down_sync(0xffffffffu, dq,  o);
        dq2 += __shfl_down_sync(0xffffffffu, dq2, o);
    }
    if ((threadIdx.x & 31) == 0) {
        atomicAdd(&g_acc[1], dq);
        atomicAdd(&g_acc[2], dq2);
    }
    if (!act) return;

    bool zcontig = (z0w <= NSI - 6);
    int zmod = z0w & 3;

    #pragma unroll
    for (int a = 0; a < 6; a++) {
        int rowx = gx[a] * NS2;
        float wq = wx[a] * q;
        #pragma unroll
        for (int b = 0; b < 6; b++) {
            int row = rowx + gy[b] * NSI;
            float wxy = wq * wy[b];
            float v0 = wxy*wz[0], v1 = wxy*wz[1], v2 = wxy*wz[2];
            float v3 = wxy*wz[3], v4 = wxy*wz[4], v5 = wxy*wz[5];
            if (zcontig) {
                float* p = g_mesh + row + z0w;
                if (zmod == 0) {
                    red4(p, v0, v1, v2, v3);
                    red2(p + 4, v4, v5);
                } else if (zmod == 2) {
                    red2(p, v0, v1);
                    red4(p + 2, v2, v3, v4, v5);
                } else if (zmod == 3) {
                    atomicAdd(p, v0);
                    red4(p + 1, v1, v2, v3, v4);
                    atomicAdd(p + 5, v5);
                } else { // zmod == 1
                    red4(p - 1, 0.f, v0, v1, v2);
                    red4(p + 3, v3, v4, v5, 0.f);
                }
            } else {
                atomicAdd(&g_mesh[row + gz[0]], v0);
                atomicAdd(&g_mesh[row + gz[1]], v1);
                atomicAdd(&g_mesh[row + gz[2]], v2);
                atomicAdd(&g_mesh[row + gz[3]], v3);
                atomicAdd(&g_mesh[row + gz[4]], v4);
                atomicAdd(&g_mesh[row + gz[5]], v5);
            }
        }
    }
}

// ================= pass A: y-DFT (real->complex), z-paired ====================
// grid (4, 120): block covers 16 ky (two groups of 8). thread: g=tid>>6 picks
// ky sub-chunk, zi=tid&63 -> z pair (2zi, 2zi+1). One LDG.64 loads both z.
__global__ void __launch_bounds__(128) passA_kernel() {
    __shared__ __align__(16) u64 tw[60 * 16];   // [y][kl], packed (cos,sin)
    int bx = blockIdx.x;          // ky base = bx*16
    int x  = blockIdx.y;
    int tid = threadIdx.x;
    for (int i = tid; i < 60 * 16; i += 128) {
        int y = i >> 4, kl = i & 15;
        int ky = bx * 16 + kl;
        float2 t = g_tw[(ky * y) % NSI];
        tw[i] = pk2(t.x, t.y);
    }
    __syncthreads();
    int g  = tid >> 6;
    int zi = tid & 63;
    if (zi >= 60) return;
    int z0 = zi * 2;
    int klbase = g * 8;
    const float* mrow = g_mesh + x * NS2 + z0;
    float2 v0  = *(const float2*)(mrow);
    float2 v60 = *(const float2*)(mrow + 60 * NSI);
    u64 acc0[8], acc1[8];
    #pragma unroll
    for (int c = 0; c < 8; c++) { acc0[c] = pk2(0.f,0.f); acc1[c] = pk2(0.f,0.f); }
    for (int yp = 1; yp < 60; yp++) {
        float2 a = *(const float2*)(mrow + yp * NSI);
        float2 b = *(const float2*)(mrow + (NSI - yp) * NSI);
        u64 uw0 = pk2(a.x + b.x, a.x - b.x);
        u64 uw1 = pk2(a.y + b.y, a.y - b.y);
        const ulonglong2* t = (const ulonglong2*)&tw[yp * 16 + klbase];
        #pragma unroll
        for (int j = 0; j < 4; j++) {
            ulonglong2 tv = t[j];
            fma2(acc0[2*j  ], uw0, tv.x);
            fma2(acc0[2*j+1], uw0, tv.y);
            fma2(acc1[2*j  ], uw1, tv.x);
            fma2(acc1[2*j+1], uw1, tv.y);
        }
    }
    #pragma unroll
    for (int c = 0; c < 8; c++) {
        int ky = bx * 16 + klbase + c;
        if (ky < RKY) {
            float sgn = (ky & 1) ? -1.f : 1.f;
            float x0, y0, x1, y1;
            upk2(acc0[c], x0, y0);
            upk2(acc1[c], x1, y1);
            float4 out = make_float4(x0 + v0.x + sgn * v60.x, y0,
                                     x1 + v0.y + sgn * v60.y, y1);
            *(float4*)&g_buf1[(x * RKY + ky) * NSI + z0] = out;
        }
    }
}

// ================= pass B: x-DFT (complex), z-paired ==========================
// grid (8, 61): block covers 16 kx (two groups of 8; kxc=15.. skipped).
// thread z pair -> LDG.128 loads both z float2s.
__global__ void __launch_bounds__(128) passB_kernel() {
    __shared__ __align__(16) u64 tw[60 * 16 * 2];   // [xp][kl]: (c,c), (-s,s)
    int bx = blockIdx.x;
    int ky = blockIdx.y;
    int tid = threadIdx.x;
    for (int i = tid; i < 60 * 16; i += 128) {
        int xp = i >> 4, kl = i & 15;
        int kx = bx * 16 + kl;
        float2 t = (kx < NSI) ? g_tw[(kx * xp) % NSI] : make_float2(0.f, 0.f);
        tw[2*i]   = pk2(t.x, t.x);
        tw[2*i+1] = pk2(-t.y, t.y);
    }
    __syncthreads();
    int g  = tid >> 6;
    int zi = tid & 63;
    int kxc = bx * 2 + g;
    if (zi >= 60 || kxc >= 15) return;
    int z0 = zi * 2;
    int klbase = g * 8;
    const float2* base = g_buf1 + ky * NSI + z0;    // x-stride = RKY*NSI float2
    float4 v0  = *(const float4*)(base);
    float4 v60 = *(const float4*)(base + 60 * (RKY * NSI));
    u64 acc0[8], acc1[8];
    #pragma unroll
    for (int c = 0; c < 8; c++) { acc0[c] = pk2(0.f,0.f); acc1[c] = pk2(0.f,0.f); }
    for (int xp = 1; xp < 60; xp++) {
        float4 a = *(const float4*)(base + xp * (RKY * NSI));
        float4 b = *(const float4*)(base + (NSI - xp) * (RKY * NSI));
        u64 u1_0 = pk2(a.x + b.x, a.y + b.y);   // (ux, uy) z0
        u64 u2_0 = pk2(a.y - b.y, a.x - b.x);   // (wy, wx) z0
        u64 u1_1 = pk2(a.z + b.z, a.w + b.w);   // z1
        u64 u2_1 = pk2(a.w - b.w, a.z - b.z);
        const ulonglong2* t = (const ulonglong2*)&tw[(xp * 16 + klbase) * 2];
        #pragma unroll
        for (int c = 0; c < 8; c++) {
            ulonglong2 tv = t[c];
            fma2(acc0[c], u1_0, tv.x);
            fma2(acc0[c], u2_0, tv.y);
            fma2(acc1[c], u1_1, tv.x);
            fma2(acc1[c], u2_1, tv.y);
        }
    }
    #pragma unroll
    for (int c = 0; c < 8; c++) {
        int kx = kxc * 8 + c;
        float sgn = (kx & 1) ? -1.f : 1.f;
        float ax, ay, bx2, by2;
        upk2(acc0[c], ax, ay);
        upk2(acc1[c], bx2, by2);
        g_buf2[z0 * NROWS + kx * RKY + ky] =
            make_float2(ax + v0.x + sgn * v60.x, ay + v0.y + sgn * v60.y);
        g_buf2[(z0 + 1) * NROWS + kx * RKY + ky] =
            make_float2(bx2 + v0.z + sgn * v60.z, by2 + v0.w + sgn * v60.w);
    }
}

// ================= pass C: z-DFT fused with Sum w*|S|^2*G, row-paired =========
// grid (6, 58): block covers 20 kz (two groups of 10). thread: row pair
// (adjacent rows -> LDG.128).
__global__ void __launch_bounds__(128) passC_kernel() {
    __shared__ __align__(16) u64 tw[60 * 20 * 2];   // [zp][kl]: (c,c), (-s,s)
    __shared__ double red[4];
    int bx = blockIdx.x;          // kz base = bx*20
    int rb = blockIdx.y;
    int tid = threadIdx.x;
    for (int i = tid; i < 60 * 20; i += 128) {
        int zp = i / 20, kl = i % 20;
        int kz = bx * 20 + kl;
        float2 t = g_tw[(kz * zp) % NSI];
        tw[2*i]   = pk2(t.x, t.x);
        tw[2*i+1] = pk2(-t.y, t.y);
    }
    __syncthreads();
    int g  = tid >> 6;
    int ri = tid & 63;
    int klbase = g * 10;
    int r0 = rb * 128 + ri * 2;
    bool act = (r0 < NROWS);      // r0 even, NROWS even -> r0+1 also valid
    u64 acc0[10], acc1[10];
    #pragma unroll
    for (int c = 0; c < 10; c++) { acc0[c] = pk2(0.f,0.f); acc1[c] = pk2(0.f,0.f); }
    float4 v0 = make_float4(0,0,0,0), v60 = make_float4(0,0,0,0);
    if (act) {
        const float2* base = g_buf2 + r0;           // z-stride = NROWS float2
        v0  = *(const float4*)(base);
        v60 = *(const float4*)(base + 60 * NROWS);
        for (int zp = 1; zp < 60; zp++) {
            float4 a = *(const float4*)(base + zp * NROWS);
            float4 b = *(const float4*)(base + (NSI - zp) * NROWS);
            u64 u1_0 = pk2(a.x + b.x, a.y + b.y);
            u64 u2_0 = pk2(a.y - b.y, a.x - b.x);
            u64 u1_1 = pk2(a.z + b.z, a.w + b.w);
            u64 u2_1 = pk2(a.w - b.w, a.z - b.z);
            const ulonglong2* t = (const ulonglong2*)&tw[(zp * 20 + klbase) * 2];
            #pragma unroll
            for (int c = 0; c < 10; c++) {
                ulonglong2 tv = t[c];
                fma2(acc0[c], u1_0, tv.x);
                fma2(acc0[c], u2_0, tv.y);
                fma2(acc1[c], u1_1, tv.x);
                fma2(acc1[c], u2_1, tv.y);
            }
        }
    }
    double contrib = 0.0;
    if (act) {
        const float twopi = 6.28318530717958647692f;
        int kx0 = r0 / RKY, ky0 = r0 % RKY;
        int r1 = r0 + 1;
        int kx1 = r1 / RKY, ky1 = r1 % RKY;
        float fmx0 = (float)((kx0 < 60) ? kx0 : kx0 - NSI);
        float fmy0 = (float)((ky0 < 60) ? ky0 : ky0 - NSI);
        float fmx1 = (float)((kx1 < 60) ? kx1 : kx1 - NSI);
        float fmy1 = (float)((ky1 < 60) ? ky1 : ky1 - NSI);
        float wgt0 = (ky0 == 0 || ky0 == 60) ? 1.0f : 2.0f;
        float wgt1 = (ky1 == 0 || ky1 == 60) ? 1.0f : 2.0f;
        #pragma unroll
        for (int c = 0; c < 10; c++) {
            int kz = bx * 20 + klbase + c;
            float sgn = (kz & 1) ? -1.f : 1.f;
            int mz = (kz < 60) ? kz : kz - NSI;
            float fmz = (float)mz;
            // row 0
            {
                float ax, ay; upk2(acc0[c], ax, ay);
                float sx = ax + v0.x + sgn * v60.x;
                float sy = ay + v0.y + sgn * v60.y;
                float k0 = twopi * (fmx0 * g_invc[0] + fmy0 * g_invc[1] + fmz * g_invc[2]);
                float k1 = twopi * (fmx0 * g_invc[3] + fmy0 * g_invc[4] + fmz * g_invc[5]);
                float k2 = twopi * (fmx0 * g_invc[6] + fmy0 * g_invc[7] + fmz * g_invc[8]);
                float ksq = k0*k0 + k1*k1 + k2*k2;
                float G = 0.f;
                if (ksq > 0.f)
                    G = 4.f * (float)PI_D * expf(-0.5f * ALPHA_F * ALPHA_F * ksq) / ksq;
                G *= wgt0;
                contrib += (double)G * ((double)sx * (double)sx +
                                        (double)sy * (double)sy);
            }
            // row 1
            {
                float ax, ay; upk2(acc1[c], ax, ay);
                float sx = ax + v0.z + sgn * v60.z;
                float sy = ay + v0.w + sgn * v60.w;
                float k0 = twopi * (fmx1 * g_invc[0] + fmy1 * g_invc[1] + fmz * g_invc[2]);
                float k1 = twopi * (fmx1 * g_invc[3] + fmy1 * g_invc[4] + fmz * g_invc[5]);
                float k2 = twopi * (fmx1 * g_invc[6] + fmy1 * g_invc[7] + fmz * g_invc[8]);
                float ksq = k0*k0 + k1*k1 + k2*k2;
                float G = 0.f;
                if (ksq > 0.f)
                    G = 4.f * (float)PI_D * expf(-0.5f * ALPHA_F * ALPHA_F * ksq) / ksq;
                G *= wgt1;
                contrib += (double)G * ((double)sx * (double)sx +
                                        (double)sy * (double)sy);
            }
        }
    }
    #pragma unroll
    for (int o = 16; o; o >>= 1)
        contrib += __shfl_down_sync(0xffffffffu, contrib, o);
    if ((tid & 31) == 0) red[tid >> 5] = contrib;
    __syncthreads();
    if (tid == 0) {
        double s = red[0] + red[1] + red[2] + red[3];
        atomicAdd(&g_acc[0], s);
    }
}

// ---------------- finalize ----------------
__global__ void final_kernel(float* out) {
    double V  = g_vol;
    double A  = g_acc[0];
    double qs = g_acc[1];
    double q2 = g_acc[2];
    double E = 0.5 * ( A / V
                     - sqrt(2.0 / PI_D) / (double)ALPHA_F * q2
                     - 2.0 * PI_D * (double)(ALPHA_F * ALPHA_F) * qs * qs / V );
    out[0] = (float)E;
}

extern "C" void kernel_launch(void* const* d_in, const int* in_sizes, int n_in,
                              void* d_out, int out_size) {
    const float* coords  = (const float*)d_in[0];
    const float* box     = (const float*)d_in[1];
    const float* charges = (const float*)d_in[2];
    int n = in_sizes[2];   // N_ATOMS

    setup_kernel<<<1, 128>>>(box);
    zero_mesh_kernel<<<((NS3 + 8)/4 + 255)/256, 256>>>();
    spread_kernel<<<(n + 127)/128, 128>>>(coords, charges, n);
    passA_kernel<<<dim3(4, NSI), 128>>>();
    passB_kernel<<<dim3(8, RKY), 128>>>();
    passC_kernel<<<dim3(6, (NROWS + 127)/128), 128>>>();
    final_kernel<<<1, 1>>>((float*)d_out);
}

// round 10
// speedup vs baseline: 1.0810x; 1.0291x over previous
#include <cuda_runtime.h>
#include <math.h>

#define NSI 120
#define NS2 (NSI*NSI)      // 14400
#define NS3 (NSI*NSI*NSI)  // 1728000
#define RKY 61             // ky 0..60 (Hermitian half, y axis)
#define NROWS (NSI*RKY)    // 7320 (kx,ky) rows
#define ALPHA_F 1.0f
#define PI_D 3.14159265358979323846

typedef unsigned long long u64;

// ---------------- scratch (static device globals; no allocation) ----------------
__device__ __align__(16) float  g_mesh[NS3 + 8];
__device__ __align__(16) float2 g_buf1[NSI*RKY*NSI];   // [(x*61+ky)*120+z]
__device__ __align__(16) float2 g_buf2[NSI*NROWS];     // z-major: [z*7320 + kx*61+ky]
__device__ float  g_invc[9];
__device__ double g_vol;
__device__ double g_acc[3];    // [0]=Sum |S|^2 G, [1]=sum q, [2]=sum q^2
__device__ float2 g_tw[NSI];   // exp(-2*pi*i*t/120)

// ---------------- packed f32x2 helpers ----------------
__device__ __forceinline__ u64 pk2(float x, float y) {
    u64 r; asm("mov.b64 %0, {%1, %2};" : "=l"(r) : "f"(x), "f"(y)); return r;
}
__device__ __forceinline__ void upk2(u64 v, float& x, float& y) {
    asm("mov.b64 {%0, %1}, %2;" : "=f"(x), "=f"(y) : "l"(v));
}
__device__ __forceinline__ void fma2(u64& d, u64 a, u64 b) {
    asm("fma.rn.f32x2 %0, %1, %2, %3;" : "=l"(d) : "l"(a), "l"(b), "l"(d));
}
__device__ __forceinline__ u64 add2(u64 a, u64 b) {
    u64 r; asm("add.rn.f32x2 %0, %1, %2;" : "=l"(r) : "l"(a), "l"(b)); return r;
}

// ---------------- vector global reductions (sm_90+) ----------------
__device__ __forceinline__ void red2(float* p, float a, float b) {
    asm volatile("red.global.add.v2.f32 [%0], {%1, %2};"
                 :: "l"(p), "f"(a), "f"(b) : "memory");
}
__device__ __forceinline__ void red4(float* p, float a, float b, float c, float d) {
    asm volatile("red.global.add.v4.f32 [%0], {%1, %2, %3, %4};"
                 :: "l"(p), "f"(a), "f"(b), "f"(c), "f"(d) : "memory");
}

// ---------------- setup ----------------
__global__ void setup_kernel(const float* __restrict__ box) {
    int t = threadIdx.x;
    if (t < NSI) {
        double ang = -2.0 * PI_D * (double)t / (double)NSI;
        g_tw[t] = make_float2((float)cos(ang), (float)sin(ang));
    }
    if (t == 0) {
        double b[9];
        for (int i = 0; i < 9; i++) b[i] = (double)box[i];
        double c00 =  (b[4]*b[8] - b[5]*b[7]);
        double c01 = -(b[3]*b[8] - b[5]*b[6]);
        double c02 =  (b[3]*b[7] - b[4]*b[6]);
        double c10 = -(b[1]*b[8] - b[2]*b[7]);
        double c11 =  (b[0]*b[8] - b[2]*b[6]);
        double c12 = -(b[0]*b[7] - b[1]*b[6]);
        double c20 =  (b[1]*b[5] - b[2]*b[4]);
        double c21 = -(b[0]*b[5] - b[2]*b[3]);
        double c22 =  (b[0]*b[4] - b[1]*b[3]);
        double det = b[0]*c00 + b[1]*c01 + b[2]*c02;
        g_invc[0] = (float)(c00/det); g_invc[1] = (float)(c10/det); g_invc[2] = (float)(c20/det);
        g_invc[3] = (float)(c01/det); g_invc[4] = (float)(c11/det); g_invc[5] = (float)(c21/det);
        g_invc[6] = (float)(c02/det); g_invc[7] = (float)(c12/det); g_invc[8] = (float)(c22/det);
        g_vol = fabs(det);
        g_acc[0] = 0.0; g_acc[1] = 0.0; g_acc[2] = 0.0;
    }
}

__global__ void zero_mesh_kernel() {
    int i = blockIdx.x * blockDim.x + threadIdx.x;
    float4* p = (float4*)g_mesh;
    if (i < (NS3 + 8)/4) p[i] = make_float4(0.f, 0.f, 0.f, 0.f);
}

// ---------------- order-6 Lagrange weights, nodes t_j = j - 2.5 ----------------
__device__ __forceinline__ void lag6(float x, float* w) {
    float d0 = x + 2.5f, d1 = x + 1.5f, d2 = x + 0.5f;
    float d3 = x - 0.5f, d4 = x - 1.5f, d5 = x - 2.5f;
    float p1 = d0, p2 = p1*d1, p3 = p2*d2, p4 = p3*d3, p5 = p4*d4;
    float s4 = d5, s3 = s4*d4, s2 = s3*d3, s1 = s2*d2, s0 = s1*d1;
    w[0] = s0      * (-1.f/120.f);
    w[1] = p1 * s1 * ( 1.f/24.f);
    w[2] = p2 * s2 * (-1.f/12.f);
    w[3] = p3 * s3 * ( 1.f/12.f);
    w[4] = p4 * s4 * (-1.f/24.f);
    w[5] = p5      * ( 1.f/120.f);
}

__device__ __forceinline__ int wrap120(int v) {
    return (v < 0) ? v + NSI : ((v >= NSI) ? v - NSI : v);
}

// ---------------- spread: one thread per atom, vector reductions --------------
__global__ void spread_kernel(const float* __restrict__ coords,
                              const float* __restrict__ charges, int n) {
    int i = blockIdx.x * blockDim.x + threadIdx.x;
    float q = 0.f;
    float wx[6], wy[6], wz[6];
    int gx[6], gy[6], gz[6];
    int z0w = 0;
    bool act = (i < n);
    if (act) {
        float c0 = coords[3*i], c1 = coords[3*i+1], c2 = coords[3*i+2];
        q = charges[i];
        float fx = c0*g_invc[0] + c1*g_invc[3] + c2*g_invc[6];
        float fy = c0*g_invc[1] + c1*g_invc[4] + c2*g_invc[7];
        float fz = c0*g_invc[2] + c1*g_invc[5] + c2*g_invc[8];
        float px = fx * (float)NSI, py = fy * (float)NSI, pz = fz * (float)NSI;
        float i0x = floorf(px), i0y = floorf(py), i0z = floorf(pz);
        lag6(px - i0x - 0.5f, wx);
        lag6(py - i0y - 0.5f, wy);
        lag6(pz - i0z - 0.5f, wz);
        int ix = (int)i0x, iy = (int)i0y, iz = (int)i0z;
        #pragma unroll
        for (int a = 0; a < 6; a++) {
            gx[a] = wrap120(ix + a - 2);
            gy[a] = wrap120(iy + a - 2);
            gz[a] = wrap120(iz + a - 2);
        }
        z0w = gz[0];
    }
    double dq = (double)q, dq2 = (double)q * (double)q;
    #pragma unroll
    for (int o = 16; o; o >>= 1) {
        dq  += __shfl_down_sync(0xffffffffu, dq,  o);
        dq2 += __shfl_down_sync(0xffffffffu, dq2, o);
    }
    if ((threadIdx.x & 31) == 0) {
        atomicAdd(&g_acc[1], dq);
        atomicAdd(&g_acc[2], dq2);
    }
    if (!act) return;

    bool zcontig = (z0w <= NSI - 6);
    int zmod = z0w & 3;

    #pragma unroll
    for (int a = 0; a < 6; a++) {
        int rowx = gx[a] * NS2;
        float wq = wx[a] * q;
        #pragma unroll
        for (int b = 0; b < 6; b++) {
            int row = rowx + gy[b] * NSI;
            float wxy = wq * wy[b];
            float v0 = wxy*wz[0], v1 = wxy*wz[1], v2 = wxy*wz[2];
            float v3 = wxy*wz[3], v4 = wxy*wz[4], v5 = wxy*wz[5];
            if (zcontig) {
                float* p = g_mesh + row + z0w;
                if (zmod == 0) {
                    red4(p, v0, v1, v2, v3);
                    red2(p + 4, v4, v5);
                } else if (zmod == 2) {
                    red2(p, v0, v1);
                    red4(p + 2, v2, v3, v4, v5);
                } else if (zmod == 3) {
                    atomicAdd(p, v0);
                    red4(p + 1, v1, v2, v3, v4);
                    atomicAdd(p + 5, v5);
                } else { // zmod == 1
                    red4(p - 1, 0.f, v0, v1, v2);
                    red4(p + 3, v3, v4, v5, 0.f);
                }
            } else {
                atomicAdd(&g_mesh[row + gz[0]], v0);
                atomicAdd(&g_mesh[row + gz[1]], v1);
                atomicAdd(&g_mesh[row + gz[2]], v2);
                atomicAdd(&g_mesh[row + gz[3]], v3);
                atomicAdd(&g_mesh[row + gz[4]], v4);
                atomicAdd(&g_mesh[row + gz[5]], v5);
            }
        }
    }
}

// ================= pass A: y-DFT (real->complex), unroll-4 load batching ======
// grid (8 ky-chunks of 8, 120 x), block 128; thread = z (coalesced).
__global__ void __launch_bounds__(128) passA_kernel() {
    __shared__ __align__(16) u64 tw8[60 * 8];   // packed (cos,sin); y=0 unused
    int kyc = blockIdx.x;
    int x   = blockIdx.y;
    int tid = threadIdx.x;
    for (int i = tid; i < 60 * 8; i += 128) {
        int y = i >> 3, c = i & 7;
        int ky = kyc * 8 + c;
        float2 t = g_tw[(ky * y) % NSI];
        tw8[i] = pk2(t.x, t.y);
    }
    __syncthreads();
    if (tid >= NSI) return;
    int z = tid;
    const float* mrow = g_mesh + x * NS2 + z;
    u64 acc[8];
    #pragma unroll
    for (int c = 0; c < 8; c++) acc[c] = pk2(0.f, 0.f);
    float v0  = mrow[0];
    float v60 = mrow[60 * NSI];
    // peel yp = 1..3
    #pragma unroll
    for (int yp = 1; yp < 4; yp++) {
        float a = mrow[yp * NSI];
        float b = mrow[(NSI - yp) * NSI];
        u64 uw = pk2(a + b, a - b);
        const ulonglong2* t = (const ulonglong2*)&tw8[yp * 8];
        #pragma unroll
        for (int j = 0; j < 4; j++) {
            ulonglong2 tv = t[j];
            fma2(acc[2*j  ], uw, tv.x);
            fma2(acc[2*j+1], uw, tv.y);
        }
    }
    // main: 14 chunks of 4, all 8 global loads batched up front
    #pragma unroll 1
    for (int yp = 4; yp < 60; yp += 4) {
        float a0 = mrow[(yp    ) * NSI];
        float a1 = mrow[(yp + 1) * NSI];
        float a2 = mrow[(yp + 2) * NSI];
        float a3 = mrow[(yp + 3) * NSI];
        float b0 = mrow[(NSI - yp    ) * NSI];
        float b1 = mrow[(NSI - yp - 1) * NSI];
        float b2 = mrow[(NSI - yp - 2) * NSI];
        float b3 = mrow[(NSI - yp - 3) * NSI];
        u64 uw0 = pk2(a0 + b0, a0 - b0);
        u64 uw1 = pk2(a1 + b1, a1 - b1);
        u64 uw2 = pk2(a2 + b2, a2 - b2);
        u64 uw3 = pk2(a3 + b3, a3 - b3);
        const ulonglong2* t0 = (const ulonglong2*)&tw8[(yp    ) * 8];
        const ulonglong2* t1 = (const ulonglong2*)&tw8[(yp + 1) * 8];
        const ulonglong2* t2 = (const ulonglong2*)&tw8[(yp + 2) * 8];
        const ulonglong2* t3 = (const ulonglong2*)&tw8[(yp + 3) * 8];
        #pragma unroll
        for (int j = 0; j < 4; j++) {
            ulonglong2 tv0 = t0[j], tv1 = t1[j], tv2 = t2[j], tv3 = t3[j];
            fma2(acc[2*j  ], uw0, tv0.x);
            fma2(acc[2*j+1], uw0, tv0.y);
            fma2(acc[2*j  ], uw1, tv1.x);
            fma2(acc[2*j+1], uw1, tv1.y);
            fma2(acc[2*j  ], uw2, tv2.x);
            fma2(acc[2*j+1], uw2, tv2.y);
            fma2(acc[2*j  ], uw3, tv3.x);
            fma2(acc[2*j+1], uw3, tv3.y);
        }
    }
    #pragma unroll
    for (int c = 0; c < 8; c++) {
        int ky = kyc * 8 + c;
        if (ky < RKY) {
            float ax, ay; upk2(acc[c], ax, ay);
            float sgn = (ky & 1) ? -1.f : 1.f;
            float sx = ax + v0 + sgn * v60;
            g_buf1[(x * RKY + ky) * NSI + z] = make_float2(sx, ay);
        }
    }
}

// ================= pass B: x-DFT (complex), unroll-2 load batching ============
// grid (15 kx-chunks of 8, 61 ky), block 128; thread = z.
__global__ void __launch_bounds__(128) passB_kernel() {
    __shared__ __align__(16) u64 tw8[60 * 8 * 2];  // per (x,kx): (c,c), (-s,s)
    int kxc = blockIdx.x;
    int ky  = blockIdx.y;
    int tid = threadIdx.x;
    for (int i = tid; i < 60 * 8; i += 128) {
        int xv = i >> 3, c = i & 7;
        int kx = kxc * 8 + c;
        float2 t = g_tw[(kx * xv) % NSI];
        tw8[2*i]   = pk2(t.x, t.x);
        tw8[2*i+1] = pk2(-t.y, t.y);
    }
    __syncthreads();
    if (tid >= NSI) return;
    int z = tid;
    u64 acc[8];
    #pragma unroll
    for (int c = 0; c < 8; c++) acc[c] = pk2(0.f, 0.f);
    const float2* col = g_buf1 + ky * NSI + z;   // stride over x = RKY*NSI
    float2 v0  = col[0];
    float2 v60 = col[60 * (RKY * NSI)];
    // peel xp = 1
    {
        float2 a = col[1 * (RKY * NSI)];
        float2 b = col[(NSI - 1) * (RKY * NSI)];
        u64 u1 = pk2(a.x + b.x, a.y + b.y);
        u64 u2 = pk2(a.y - b.y, a.x - b.x);
        const ulonglong2* t = (const ulonglong2*)&tw8[1 * 16];
        #pragma unroll
        for (int c = 0; c < 8; c++) {
            ulonglong2 tv = t[c];
            fma2(acc[c], u1, tv.x);
            fma2(acc[c], u2, tv.y);
        }
    }
    // main: 29 chunks of 2, 4 global loads batched
    #pragma unroll 1
    for (int xp = 2; xp < 60; xp += 2) {
        float2 a0 = col[(xp    ) * (RKY * NSI)];
        float2 a1 = col[(xp + 1) * (RKY * NSI)];
        float2 b0 = col[(NSI - xp    ) * (RKY * NSI)];
        float2 b1 = col[(NSI - xp - 1) * (RKY * NSI)];
        u64 u1_0 = pk2(a0.x + b0.x, a0.y + b0.y);
        u64 u2_0 = pk2(a0.y - b0.y, a0.x - b0.x);
        u64 u1_1 = pk2(a1.x + b1.x, a1.y + b1.y);
        u64 u2_1 = pk2(a1.y - b1.y, a1.x - b1.x);
        const ulonglong2* t0 = (const ulonglong2*)&tw8[(xp    ) * 16];
        const ulonglong2* t1 = (const ulonglong2*)&tw8[(xp + 1) * 16];
        #pragma unroll
        for (int c = 0; c < 8; c++) {
            ulonglong2 tv0 = t0[c], tv1 = t1[c];
            fma2(acc[c], u1_0, tv0.x);
            fma2(acc[c], u2_0, tv0.y);
            fma2(acc[c], u1_1, tv1.x);
            fma2(acc[c], u2_1, tv1.y);
        }
    }
    #pragma unroll
    for (int c = 0; c < 8; c++) {
        int kx = kxc * 8 + c;
        float ax, ay; upk2(acc[c], ax, ay);
        float sgn = (kx & 1) ? -1.f : 1.f;
        float sx = ax + v0.x + sgn * v60.x;
        float sy = ay + v0.y + sgn * v60.y;
        g_buf2[z * NROWS + kx * RKY + ky] = make_float2(sx, sy);
    }
}

// ================= pass C: z-DFT fused with Sum w*|S|^2*G, unroll-2 ===========
// grid (12 kz-chunks of 10, 58 row-blocks), block 128; thread = row.
__global__ void __launch_bounds__(128) passC_kernel() {
    __shared__ __align__(16) u64 tw10[60 * 10 * 2];  // per (z,kz): (c,c), (-s,s)
    __shared__ double red[4];
    int kzc = blockIdx.x;          // kz = kzc*10 + c
    int r   = blockIdx.y * 128 + threadIdx.x;
    int tid = threadIdx.x;
    for (int i = tid; i < 60 * 10; i += 128) {
        int z = i / 10, c = i % 10;
        int kz = kzc * 10 + c;
        float2 t = g_tw[(kz * z) % NSI];
        tw10[2*i]   = pk2(t.x, t.x);
        tw10[2*i+1] = pk2(-t.y, t.y);
    }
    __syncthreads();
    bool act = (r < NROWS);
    u64 acc[10];
    #pragma unroll
    for (int c = 0; c < 10; c++) acc[c] = pk2(0.f, 0.f);
    float2 v0 = make_float2(0.f, 0.f), v60 = make_float2(0.f, 0.f);
    if (act) {
        const float2* col = g_buf2 + r;   // stride over z = NROWS
        v0  = col[0];
        v60 = col[60 * NROWS];
        // peel zp = 1
        {
            float2 a = col[1 * NROWS];
            float2 b = col[(NSI - 1) * NROWS];
            u64 u1 = pk2(a.x + b.x, a.y + b.y);
            u64 u2 = pk2(a.y - b.y, a.x - b.x);
            const ulonglong2* t = (const ulonglong2*)&tw10[1 * 20];
            #pragma unroll
            for (int c = 0; c < 10; c++) {
                ulonglong2 tv = t[c];
                fma2(acc[c], u1, tv.x);
                fma2(acc[c], u2, tv.y);
            }
        }
        #pragma unroll 1
        for (int zp = 2; zp < 60; zp += 2) {
            float2 a0 = col[(zp    ) * NROWS];
            float2 a1 = col[(zp + 1) * NROWS];
            float2 b0 = col[(NSI - zp    ) * NROWS];
            float2 b1 = col[(NSI - zp - 1) * NROWS];
            u64 u1_0 = pk2(a0.x + b0.x, a0.y + b0.y);
            u64 u2_0 = pk2(a0.y - b0.y, a0.x - b0.x);
            u64 u1_1 = pk2(a1.x + b1.x, a1.y + b1.y);
            u64 u2_1 = pk2(a1.y - b1.y, a1.x - b1.x);
            const ulonglong2* t0 = (const ulonglong2*)&tw10[(zp    ) * 20];
            const ulonglong2* t1 = (const ulonglong2*)&tw10[(zp + 1) * 20];
            #pragma unroll
            for (int c = 0; c < 10; c++) {
                ulonglong2 tv0 = t0[c], tv1 = t1[c];
                fma2(acc[c], u1_0, tv0.x);
                fma2(acc[c], u2_0, tv0.y);
                fma2(acc[c], u1_1, tv1.x);
                fma2(acc[c], u2_1, tv1.y);
            }
        }
    }
    double contrib = 0.0;
    if (act) {
        int kx = r / RKY, ky = r % RKY;
        int mx = (kx < 60) ? kx : kx - NSI;
        int my = (ky < 60) ? ky : ky - NSI;   // ky==60 -> -60
        float wgt = (ky == 0 || ky == 60) ? 1.0f : 2.0f;
        float fmx = (float)mx, fmy = (float)my;
        const float twopi = 6.28318530717958647692f;
        #pragma unroll
        for (int c = 0; c < 10; c++) {
            int kz = kzc * 10 + c;
            float sgn = (kz & 1) ? -1.f : 1.f;
            float ax, ay; upk2(acc[c], ax, ay);
            float sx = ax + v0.x + sgn * v60.x;
            float sy = ay + v0.y + sgn * v60.y;
            int mz = (kz < 60) ? kz : kz - NSI;
            float fmz = (float)mz;
            float k0 = twopi * (fmx * g_invc[0] + fmy * g_invc[1] + fmz * g_invc[2]);
            float k1 = twopi * (fmx * g_invc[3] + fmy * g_invc[4] + fmz * g_invc[5]);
            float k2 = twopi * (fmx * g_invc[6] + fmy * g_invc[7] + fmz * g_invc[8]);
            float ksq = k0*k0 + k1*k1 + k2*k2;
            float G = 0.f;
            if (ksq > 0.f)
                G = 4.f * (float)PI_D * expf(-0.5f * ALPHA_F * ALPHA_F * ksq) / ksq;
            G *= wgt;
            contrib += (double)G * ((double)sx * (double)sx +
                                    (double)sy * (double)sy);
        }
    }
    #pragma unroll
    for (int o = 16; o; o >>= 1)
        contrib += __shfl_down_sync(0xffffffffu, contrib, o);
    if ((tid & 31) == 0) red[tid >> 5] = contrib;
    __syncthreads();
    if (tid == 0) {
        double s = red[0] + red[1] + red[2] + red[3];
        atomicAdd(&g_acc[0], s);
    }
}

// ---------------- finalize ----------------
__global__ void final_kernel(float* out) {
    double V  = g_vol;
    double A  = g_acc[0];
    double qs = g_acc[1];
    double q2 = g_acc[2];
    double E = 0.5 * ( A / V
                     - sqrt(2.0 / PI_D) / (double)ALPHA_F * q2
                     - 2.0 * PI_D * (double)(ALPHA_F * ALPHA_F) * qs * qs / V );
    out[0] = (float)E;
}

extern "C" void kernel_launch(void* const* d_in, const int* in_sizes, int n_in,
                              void* d_out, int out_size) {
    const float* coords  = (const float*)d_in[0];
    const float* box     = (const float*)d_in[1];
    const float* charges = (const float*)d_in[2];
    int n = in_sizes[2];   // N_ATOMS

    setup_kernel<<<1, 128>>>(box);
    zero_mesh_kernel<<<((NS3 + 8)/4 + 255)/256, 256>>>();
    spread_kernel<<<(n + 127)/128, 128>>>(coords, charges, n);
    passA_kernel<<<dim3(8, NSI), 128>>>();
    passB_kernel<<<dim3(15, RKY), 128>>>();
    passC_kernel<<<dim3(12, (NROWS + 127)/128), 128>>>();
    final_kernel<<<1, 1>>>((float*)d_out);
}